// round 2
// baseline (speedup 1.0000x reference)
#include <cuda_runtime.h>

// GRU_67714454389230: 2-layer GRU (H=12, IN=18) + fc(12->1), B=4096, T=512.
// Round 2: 16 lanes per batch element (12 active, 1 hidden unit per lane).
// 65536 threads = 2048 warps (~3.5 warps/SMSP) vs 512 before — the Round-1
// kernel was latency-bound at issue=28% / occ=6.2% with register spills
// (regs=255). Weights in shared, transposed [gate][chunk][unit] so active
// lanes read consecutive float4s (conflict-free broadcast to both groups).

static constexpr int IN_DIM = 18;
static constexpr int HID    = 12;
static constexpr int BATCH  = 4096;
static constexpr int SEQ    = 512;
static constexpr int THREADS = 128;                 // 8 batch elements / block
static constexpr int GRID    = BATCH / (THREADS / 16);  // 512 blocks

__device__ __forceinline__ float fast_sig(float x) {
    return __fdividef(1.0f, 1.0f + __expf(-x));
}
__device__ __forceinline__ float fast_tanh(float x) {
    return 1.0f - __fdividef(2.0f, __expf(2.0f * x) + 1.0f);
}

__global__ __launch_bounds__(THREADS, 4)
void gru_scan_kernel(const float* __restrict__ x,
                     const float* __restrict__ w_ih0, const float* __restrict__ w_hh0,
                     const float* __restrict__ b_ih0, const float* __restrict__ b_hh0,
                     const float* __restrict__ w_ih1, const float* __restrict__ w_hh1,
                     const float* __restrict__ b_ih1, const float* __restrict__ b_hh1,
                     const float* __restrict__ fc_w, const float* __restrict__ fc_b,
                     float* __restrict__ out)
{
    // Transposed shared weights: [gate][k-chunk][unit]. Active lanes (unit
    // 0..11) read 12 consecutive float4s per access -> conflict-free.
    __shared__ float4 s_ih0_4[3][4][HID];   // k = 0..15 of 18
    __shared__ float2 s_ih0_2[3][HID];      // k = 16,17
    __shared__ float4 s_hh0_4[3][3][HID];   // k = 0..11
    __shared__ float4 s_ih1_4[3][3][HID];
    __shared__ float4 s_hh1_4[3][3][HID];

    const int tid = threadIdx.x;

    // One thread per (gate,unit) row: 36 rows, transposing loads.
    if (tid < 36) {
        const int gate = tid / HID, u = tid % HID;
        const int row = gate * HID + u;
        const float* wi0 = w_ih0 + row * IN_DIM;
#pragma unroll
        for (int c = 0; c < 4; ++c)
            s_ih0_4[gate][c][u] = make_float4(wi0[4*c], wi0[4*c+1], wi0[4*c+2], wi0[4*c+3]);
        s_ih0_2[gate][u] = make_float2(wi0[16], wi0[17]);
        const float* wh0 = w_hh0 + row * HID;
        const float* wi1 = w_ih1 + row * HID;
        const float* wh1 = w_hh1 + row * HID;
#pragma unroll
        for (int c = 0; c < 3; ++c) {
            s_hh0_4[gate][c][u] = make_float4(wh0[4*c], wh0[4*c+1], wh0[4*c+2], wh0[4*c+3]);
            s_ih1_4[gate][c][u] = make_float4(wi1[4*c], wi1[4*c+1], wi1[4*c+2], wi1[4*c+3]);
            s_hh1_4[gate][c][u] = make_float4(wh1[4*c], wh1[4*c+1], wh1[4*c+2], wh1[4*c+3]);
        }
    }
    __syncthreads();

    const int batch = blockIdx.x * (THREADS / 16) + (tid >> 4);
    const int sub   = tid & 15;               // lane within group
    const int u     = (sub < HID) ? sub : HID - 1;   // clamp idle lanes (results unused)

    // Biases. r,z gates: i- and h-bias always summed -> combine.
    const float brz0_r = b_ih0[u]          + b_hh0[u];
    const float brz0_z = b_ih0[HID + u]    + b_hh0[HID + u];
    const float bin0   = b_ih0[2*HID + u];
    const float bhn0   = b_hh0[2*HID + u];
    const float brz1_r = b_ih1[u]          + b_hh1[u];
    const float brz1_z = b_ih1[HID + u]    + b_hh1[HID + u];
    const float bin1   = b_ih1[2*HID + u];
    const float bhn1   = b_hh1[2*HID + u];

    float fcw[HID];
#pragma unroll
    for (int k = 0; k < HID; ++k) fcw[k] = fc_w[k];
    const float fcb = fc_b[0];

    float h1v[HID], h2v[HID];
#pragma unroll
    for (int k = 0; k < HID; ++k) { h1v[k] = 0.0f; h2v[k] = 0.0f; }

    const float2* xp = (const float2*)(x + (size_t)batch * SEQ * IN_DIM);  // 18 even -> 8B ok
    float* op = out + (size_t)batch * SEQ;

    float2 xn[9];
#pragma unroll
    for (int i = 0; i < 9; ++i) xn[i] = xp[i];

    for (int t = 0; t < SEQ; ++t) {
        float xv[IN_DIM];
#pragma unroll
        for (int i = 0; i < 9; ++i) { xv[2*i] = xn[i].x; xv[2*i+1] = xn[i].y; }

        const float2* xnext = xp + (size_t)(t + 1) * 9;
#pragma unroll
        for (int i = 0; i < 9; ++i)
            xn[i] = (t + 1 < SEQ) ? xnext[i] : make_float2(0.0f, 0.0f);

        // ---- layer-2 hh projection first: depends only on PREV h2 ----
        float a2r = brz1_r, a2z = brz1_z, a2hn = bhn1;
#pragma unroll
        for (int c = 0; c < 3; ++c) {
            const float4 wr = s_hh1_4[0][c][u];
            const float4 wz = s_hh1_4[1][c][u];
            const float4 wn = s_hh1_4[2][c][u];
            const float p0 = h2v[4*c], p1 = h2v[4*c+1], p2 = h2v[4*c+2], p3 = h2v[4*c+3];
            a2r  = fmaf(p0, wr.x, a2r);  a2r  = fmaf(p1, wr.y, a2r);
            a2r  = fmaf(p2, wr.z, a2r);  a2r  = fmaf(p3, wr.w, a2r);
            a2z  = fmaf(p0, wz.x, a2z);  a2z  = fmaf(p1, wz.y, a2z);
            a2z  = fmaf(p2, wz.z, a2z);  a2z  = fmaf(p3, wz.w, a2z);
            a2hn = fmaf(p0, wn.x, a2hn); a2hn = fmaf(p1, wn.y, a2hn);
            a2hn = fmaf(p2, wn.z, a2hn); a2hn = fmaf(p3, wn.w, a2hn);
        }

        // ---- layer 1 ----
        float a1r = brz0_r, a1z = brz0_z, a1in = bin0, a1hn = bhn0;
        // input projection (k=0..17)
#pragma unroll
        for (int c = 0; c < 4; ++c) {
            const float4 wr = s_ih0_4[0][c][u];
            const float4 wz = s_ih0_4[1][c][u];
            const float4 wn = s_ih0_4[2][c][u];
            const float x0 = xv[4*c], x1 = xv[4*c+1], x2 = xv[4*c+2], x3 = xv[4*c+3];
            a1r  = fmaf(x0, wr.x, a1r);  a1r  = fmaf(x1, wr.y, a1r);
            a1r  = fmaf(x2, wr.z, a1r);  a1r  = fmaf(x3, wr.w, a1r);
            a1z  = fmaf(x0, wz.x, a1z);  a1z  = fmaf(x1, wz.y, a1z);
            a1z  = fmaf(x2, wz.z, a1z);  a1z  = fmaf(x3, wz.w, a1z);
            a1in = fmaf(x0, wn.x, a1in); a1in = fmaf(x1, wn.y, a1in);
            a1in = fmaf(x2, wn.z, a1in); a1in = fmaf(x3, wn.w, a1in);
        }
        {
            const float2 wr = s_ih0_2[0][u];
            const float2 wz = s_ih0_2[1][u];
            const float2 wn = s_ih0_2[2][u];
            a1r  = fmaf(xv[16], wr.x, a1r);  a1r  = fmaf(xv[17], wr.y, a1r);
            a1z  = fmaf(xv[16], wz.x, a1z);  a1z  = fmaf(xv[17], wz.y, a1z);
            a1in = fmaf(xv[16], wn.x, a1in); a1in = fmaf(xv[17], wn.y, a1in);
        }
        // hidden projection (k=0..11)
#pragma unroll
        for (int c = 0; c < 3; ++c) {
            const float4 wr = s_hh0_4[0][c][u];
            const float4 wz = s_hh0_4[1][c][u];
            const float4 wn = s_hh0_4[2][c][u];
            const float p0 = h1v[4*c], p1 = h1v[4*c+1], p2 = h1v[4*c+2], p3 = h1v[4*c+3];
            a1r  = fmaf(p0, wr.x, a1r);  a1r  = fmaf(p1, wr.y, a1r);
            a1r  = fmaf(p2, wr.z, a1r);  a1r  = fmaf(p3, wr.w, a1r);
            a1z  = fmaf(p0, wz.x, a1z);  a1z  = fmaf(p1, wz.y, a1z);
            a1z  = fmaf(p2, wz.z, a1z);  a1z  = fmaf(p3, wz.w, a1z);
            a1hn = fmaf(p0, wn.x, a1hn); a1hn = fmaf(p1, wn.y, a1hn);
            a1hn = fmaf(p2, wn.z, a1hn); a1hn = fmaf(p3, wn.w, a1hn);
        }
        {
            const float r = fast_sig(a1r);
            const float z = fast_sig(a1z);
            const float n = fast_tanh(fmaf(r, a1hn, a1in));
            const float hp = h1v[u];
            const float hn1 = fmaf(z, hp - n, n);      // (1-z)*n + z*h
#pragma unroll
            for (int k = 0; k < HID; ++k)
                h1v[k] = __shfl_sync(0xffffffffu, hn1, k, 16);
        }

        // ---- layer 2 ih projection on fresh h1 ----
        float a2in = bin1;
#pragma unroll
        for (int c = 0; c < 3; ++c) {
            const float4 wr = s_ih1_4[0][c][u];
            const float4 wz = s_ih1_4[1][c][u];
            const float4 wn = s_ih1_4[2][c][u];
            const float p0 = h1v[4*c], p1 = h1v[4*c+1], p2 = h1v[4*c+2], p3 = h1v[4*c+3];
            a2r  = fmaf(p0, wr.x, a2r);  a2r  = fmaf(p1, wr.y, a2r);
            a2r  = fmaf(p2, wr.z, a2r);  a2r  = fmaf(p3, wr.w, a2r);
            a2z  = fmaf(p0, wz.x, a2z);  a2z  = fmaf(p1, wz.y, a2z);
            a2z  = fmaf(p2, wz.z, a2z);  a2z  = fmaf(p3, wz.w, a2z);
            a2in = fmaf(p0, wn.x, a2in); a2in = fmaf(p1, wn.y, a2in);
            a2in = fmaf(p2, wn.z, a2in); a2in = fmaf(p3, wn.w, a2in);
        }
        {
            const float r = fast_sig(a2r);
            const float z = fast_sig(a2z);
            const float n = fast_tanh(fmaf(r, a2hn, a2in));
            const float hp = h2v[u];
            const float hn2 = fmaf(z, hp - n, n);
#pragma unroll
            for (int k = 0; k < HID; ++k)
                h2v[k] = __shfl_sync(0xffffffffu, hn2, k, 16);
        }

        // ---- fc ----
        if (sub == 0) {
            float o = fcb;
#pragma unroll
            for (int k = 0; k < HID; ++k) o = fmaf(fcw[k], h2v[k], o);
            op[t] = o;
        }
    }
}

extern "C" void kernel_launch(void* const* d_in, const int* in_sizes, int n_in,
                              void* d_out, int out_size) {
    const float* x     = (const float*)d_in[0];
    const float* w_ih0 = (const float*)d_in[1];
    const float* w_hh0 = (const float*)d_in[2];
    const float* b_ih0 = (const float*)d_in[3];
    const float* b_hh0 = (const float*)d_in[4];
    const float* w_ih1 = (const float*)d_in[5];
    const float* w_hh1 = (const float*)d_in[6];
    const float* b_ih1 = (const float*)d_in[7];
    const float* b_hh1 = (const float*)d_in[8];
    const float* fc_w  = (const float*)d_in[9];
    const float* fc_b  = (const float*)d_in[10];
    float* out = (float*)d_out;

    gru_scan_kernel<<<GRID, THREADS>>>(x, w_ih0, w_hh0, b_ih0, b_hh0,
                                       w_ih1, w_hh1, b_ih1, b_hh1,
                                       fc_w, fc_b, out);
}

// round 3
// speedup vs baseline: 1.6883x; 1.6883x over previous
#include <cuda_runtime.h>

// GRU_67714454389230: 2-layer GRU (H=12, IN=18) + fc(12->1), B=4096, T=512.
// Round 3:
//  - Kernel 1 precomputes gi0 = x @ W_ih0^T + b_ih0 (fully parallel, no scan).
//  - Kernel 2 does the recurrence: 16-lane groups, 12 active lanes (1 hidden
//    unit each), TWO batch elements per group (weight LDS amortized 2x, ILP 2x).
//    h-vectors exchanged via shared memory (STS + LDS.128) instead of shuffles.
//    Idle lanes 12/13 compute the fc output.

static constexpr int IN_DIM = 18;
static constexpr int HID    = 12;
static constexpr int BATCH  = 4096;
static constexpr int SEQ    = 512;

// ---------------- scratch for precomputed layer-1 input projections ----------
// layout: [B][T][3][12]  (gate-major r,z,n; unit minor)
__device__ float g_gi0[(size_t)BATCH * SEQ * 36];

// ---------------- kernel 1: gi0 precompute ----------------------------------
static constexpr int ROWS_PER_BLOCK = 64;   // (b,t) rows per block

__global__ __launch_bounds__(128, 8)
void gi0_kernel(const float* __restrict__ x,
                const float* __restrict__ w_ih0,
                const float* __restrict__ b_ih0)
{
    __shared__ float sx[ROWS_PER_BLOCK * IN_DIM];   // 64 rows x 18
    __shared__ float sw[36][IN_DIM];
    __shared__ float sb[36];

    const int tid = threadIdx.x;
    for (int i = tid; i < 36 * IN_DIM; i += 128) sw[i / IN_DIM][i % IN_DIM] = w_ih0[i];
    if (tid < 36) sb[tid] = b_ih0[tid];

    const size_t row0 = (size_t)blockIdx.x * ROWS_PER_BLOCK;
    // 64*18 = 1152 floats contiguous; block base is 16B aligned (1152*4 mult of 16)
    const float4* xg = (const float4*)(x + row0 * IN_DIM);
    float4* sxf = (float4*)sx;
    for (int i = tid; i < (ROWS_PER_BLOCK * IN_DIM) / 4; i += 128) sxf[i] = xg[i];
    __syncthreads();

    const int row   = tid >> 1;          // 0..63
    const int jbase = (tid & 1) * 18;    // 0 or 18

    float xr[IN_DIM];
#pragma unroll
    for (int k = 0; k < IN_DIM; ++k) xr[k] = sx[row * IN_DIM + k];

    float outv[18];
#pragma unroll
    for (int jj = 0; jj < 18; ++jj) {
        const int j = jbase + jj;
        float a = sb[j];
#pragma unroll
        for (int k = 0; k < IN_DIM; ++k) a = fmaf(xr[k], sw[j][k], a);
        outv[jj] = a;
    }
    float* og = g_gi0 + (row0 + row) * 36 + jbase;   // 8B aligned
#pragma unroll
    for (int jj = 0; jj < 18; jj += 2)
        *(float2*)(og + jj) = make_float2(outv[jj], outv[jj + 1]);
}

// ---------------- kernel 2: recurrent scan -----------------------------------
static constexpr int S_THREADS = 128;            // 8 groups of 16 lanes
static constexpr int GROUPS    = 8;              // per block
static constexpr int S_GRID    = BATCH / (GROUPS * 2);   // 2 batches/group -> 256

__device__ __forceinline__ float fast_sig(float x) {
    return __fdividef(1.0f, 1.0f + __expf(-x));
}
__device__ __forceinline__ float fast_tanh(float x) {
    return 1.0f - __fdividef(2.0f, __expf(2.0f * x) + 1.0f);
}

__global__ __launch_bounds__(S_THREADS, 4)
void gru_scan_kernel(const float* __restrict__ w_hh0, const float* __restrict__ b_hh0,
                     const float* __restrict__ w_ih1, const float* __restrict__ w_hh1,
                     const float* __restrict__ b_ih1, const float* __restrict__ b_hh1,
                     const float* __restrict__ fc_w, const float* __restrict__ fc_b,
                     float* __restrict__ out)
{
    // weights transposed [gate][k-chunk][unit] -> 12 consecutive float4 per access
    __shared__ float4 s_hh0[3][3][HID];
    __shared__ float4 s_ih1[3][3][HID];
    __shared__ float4 s_hh1[3][3][HID];
    __shared__ float  s_h1[GROUPS][2][HID];     // [group][batch][unit]
    __shared__ float  s_h2[GROUPS][2][HID];

    const int tid = threadIdx.x;
    if (tid < 36) {
        const int gate = tid / HID, uu = tid % HID;
        const int row = gate * HID + uu;
        const float* wh0 = w_hh0 + row * HID;
        const float* wi1 = w_ih1 + row * HID;
        const float* wh1 = w_hh1 + row * HID;
#pragma unroll
        for (int c = 0; c < 3; ++c) {
            s_hh0[gate][c][uu] = make_float4(wh0[4*c], wh0[4*c+1], wh0[4*c+2], wh0[4*c+3]);
            s_ih1[gate][c][uu] = make_float4(wi1[4*c], wi1[4*c+1], wi1[4*c+2], wi1[4*c+3]);
            s_hh1[gate][c][uu] = make_float4(wh1[4*c], wh1[4*c+1], wh1[4*c+2], wh1[4*c+3]);
        }
    }
    for (int i = tid; i < GROUPS * 2 * HID; i += S_THREADS)
        ((float*)s_h2)[i] = 0.0f;
    __syncthreads();

    const int grp_l = tid >> 4;                 // group in block
    const int sub   = tid & 15;
    const int u     = (sub < HID) ? sub : HID - 1;
    const int grp   = blockIdx.x * GROUPS + grp_l;
    const int b0    = grp * 2;
    const int b1    = b0 + 1;

    // biases
    const float bh0r = b_hh0[u], bh0z = b_hh0[HID + u], bh0n = b_hh0[2*HID + u];
    const float b2r  = b_ih1[u]       + b_hh1[u];
    const float b2z  = b_ih1[HID + u] + b_hh1[HID + u];
    const float b2in = b_ih1[2*HID + u];
    const float b2hn = b_hh1[2*HID + u];

    float fcw[HID];
#pragma unroll
    for (int k = 0; k < HID; ++k) fcw[k] = fc_w[k];
    const float fcb = fc_b[0];

    const float* giA = g_gi0 + (size_t)b0 * SEQ * 36;
    const float* giB = g_gi0 + (size_t)b1 * SEQ * 36;

    float h1a[HID], h1b[HID];
#pragma unroll
    for (int k = 0; k < HID; ++k) { h1a[k] = 0.0f; h1b[k] = 0.0f; }
    float hp2a = 0.0f, hp2b = 0.0f;

    // prefetch gi0 for t=0
    float gAr = giA[u], gAz = giA[HID + u], gAn = giA[2*HID + u];
    float gBr = giB[u], gBz = giB[HID + u], gBn = giB[2*HID + u];

    for (int t = 0; t < SEQ; ++t) {
        const float cAr = gAr, cAz = gAz, cAn = gAn;
        const float cBr = gBr, cBz = gBz, cBn = gBn;
        {   // prefetch t+1 (clamped)
            const int tn = (t + 1 < SEQ) ? (t + 1) : t;
            const float* pA = giA + (size_t)tn * 36;
            const float* pB = giB + (size_t)tn * 36;
            gAr = pA[u]; gAz = pA[HID + u]; gAn = pA[2*HID + u];
            gBr = pB[u]; gBz = pB[HID + u]; gBn = pB[2*HID + u];
        }

        // ---- A) layer-2 hidden projection from PREVIOUS h2 (in shared) ----
        float a2r_a = b2r, a2z_a = b2z, a2n_a = b2hn;
        float a2r_b = b2r, a2z_b = b2z, a2n_b = b2hn;
        {
            const float4 qa0 = *(const float4*)&s_h2[grp_l][0][0];
            const float4 qa1 = *(const float4*)&s_h2[grp_l][0][4];
            const float4 qa2 = *(const float4*)&s_h2[grp_l][0][8];
            const float4 qb0 = *(const float4*)&s_h2[grp_l][1][0];
            const float4 qb1 = *(const float4*)&s_h2[grp_l][1][4];
            const float4 qb2 = *(const float4*)&s_h2[grp_l][1][8];
            const float4 ha[3] = {qa0, qa1, qa2};
            const float4 hb[3] = {qb0, qb1, qb2};
#pragma unroll
            for (int c = 0; c < 3; ++c) {
                const float4 wr = s_hh1[0][c][u];
                const float4 wz = s_hh1[1][c][u];
                const float4 wn = s_hh1[2][c][u];
                a2r_a = fmaf(ha[c].x, wr.x, a2r_a); a2r_a = fmaf(ha[c].y, wr.y, a2r_a);
                a2r_a = fmaf(ha[c].z, wr.z, a2r_a); a2r_a = fmaf(ha[c].w, wr.w, a2r_a);
                a2z_a = fmaf(ha[c].x, wz.x, a2z_a); a2z_a = fmaf(ha[c].y, wz.y, a2z_a);
                a2z_a = fmaf(ha[c].z, wz.z, a2z_a); a2z_a = fmaf(ha[c].w, wz.w, a2z_a);
                a2n_a = fmaf(ha[c].x, wn.x, a2n_a); a2n_a = fmaf(ha[c].y, wn.y, a2n_a);
                a2n_a = fmaf(ha[c].z, wn.z, a2n_a); a2n_a = fmaf(ha[c].w, wn.w, a2n_a);
                a2r_b = fmaf(hb[c].x, wr.x, a2r_b); a2r_b = fmaf(hb[c].y, wr.y, a2r_b);
                a2r_b = fmaf(hb[c].z, wr.z, a2r_b); a2r_b = fmaf(hb[c].w, wr.w, a2r_b);
                a2z_b = fmaf(hb[c].x, wz.x, a2z_b); a2z_b = fmaf(hb[c].y, wz.y, a2z_b);
                a2z_b = fmaf(hb[c].z, wz.z, a2z_b); a2z_b = fmaf(hb[c].w, wz.w, a2z_b);
                a2n_b = fmaf(hb[c].x, wn.x, a2n_b); a2n_b = fmaf(hb[c].y, wn.y, a2n_b);
                a2n_b = fmaf(hb[c].z, wn.z, a2n_b); a2n_b = fmaf(hb[c].w, wn.w, a2n_b);
            }
        }

        // ---- B) layer-1 hidden projection (h1 in registers) + activations ----
        float hn1_a, hn1_b;
        {
            float ar_a = bh0r, az_a = bh0z, an_a = bh0n;
            float ar_b = bh0r, az_b = bh0z, an_b = bh0n;
#pragma unroll
            for (int c = 0; c < 3; ++c) {
                const float4 wr = s_hh0[0][c][u];
                const float4 wz = s_hh0[1][c][u];
                const float4 wn = s_hh0[2][c][u];
                const float p0 = h1a[4*c], p1 = h1a[4*c+1], p2 = h1a[4*c+2], p3 = h1a[4*c+3];
                const float q0 = h1b[4*c], q1 = h1b[4*c+1], q2 = h1b[4*c+2], q3 = h1b[4*c+3];
                ar_a = fmaf(p0, wr.x, ar_a); ar_a = fmaf(p1, wr.y, ar_a);
                ar_a = fmaf(p2, wr.z, ar_a); ar_a = fmaf(p3, wr.w, ar_a);
                az_a = fmaf(p0, wz.x, az_a); az_a = fmaf(p1, wz.y, az_a);
                az_a = fmaf(p2, wz.z, az_a); az_a = fmaf(p3, wz.w, az_a);
                an_a = fmaf(p0, wn.x, an_a); an_a = fmaf(p1, wn.y, an_a);
                an_a = fmaf(p2, wn.z, an_a); an_a = fmaf(p3, wn.w, an_a);
                ar_b = fmaf(q0, wr.x, ar_b); ar_b = fmaf(q1, wr.y, ar_b);
                ar_b = fmaf(q2, wr.z, ar_b); ar_b = fmaf(q3, wr.w, ar_b);
                az_b = fmaf(q0, wz.x, az_b); az_b = fmaf(q1, wz.y, az_b);
                az_b = fmaf(q2, wz.z, az_b); az_b = fmaf(q3, wz.w, az_b);
                an_b = fmaf(q0, wn.x, an_b); an_b = fmaf(q1, wn.y, an_b);
                an_b = fmaf(q2, wn.z, an_b); an_b = fmaf(q3, wn.w, an_b);
            }
            const float r_a = fast_sig(cAr + ar_a);
            const float z_a = fast_sig(cAz + az_a);
            const float n_a = fast_tanh(fmaf(r_a, an_a, cAn));
            hn1_a = fmaf(z_a, h1a[u] - n_a, n_a);
            const float r_b = fast_sig(cBr + ar_b);
            const float z_b = fast_sig(cBz + az_b);
            const float n_b = fast_tanh(fmaf(r_b, an_b, cBn));
            hn1_b = fmaf(z_b, h1b[u] - n_b, n_b);
        }

        // ---- C) exchange h1 through shared ----
        if (sub < HID) {
            s_h1[grp_l][0][u] = hn1_a;
            s_h1[grp_l][1][u] = hn1_b;
        }
        __syncwarp();
        {
            const float4 a0 = *(const float4*)&s_h1[grp_l][0][0];
            const float4 a1 = *(const float4*)&s_h1[grp_l][0][4];
            const float4 a2 = *(const float4*)&s_h1[grp_l][0][8];
            const float4 b0f = *(const float4*)&s_h1[grp_l][1][0];
            const float4 b1f = *(const float4*)&s_h1[grp_l][1][4];
            const float4 b2f = *(const float4*)&s_h1[grp_l][1][8];
            h1a[0]=a0.x; h1a[1]=a0.y; h1a[2]=a0.z; h1a[3]=a0.w;
            h1a[4]=a1.x; h1a[5]=a1.y; h1a[6]=a1.z; h1a[7]=a1.w;
            h1a[8]=a2.x; h1a[9]=a2.y; h1a[10]=a2.z; h1a[11]=a2.w;
            h1b[0]=b0f.x; h1b[1]=b0f.y; h1b[2]=b0f.z; h1b[3]=b0f.w;
            h1b[4]=b1f.x; h1b[5]=b1f.y; h1b[6]=b1f.z; h1b[7]=b1f.w;
            h1b[8]=b2f.x; h1b[9]=b2f.y; h1b[10]=b2f.z; h1b[11]=b2f.w;
        }

        // ---- D) layer-2 input projection on fresh h1 + activations ----
        float hn2_a, hn2_b;
        {
            float ai_a = b2in, ai_b = b2in;
#pragma unroll
            for (int c = 0; c < 3; ++c) {
                const float4 wr = s_ih1[0][c][u];
                const float4 wz = s_ih1[1][c][u];
                const float4 wn = s_ih1[2][c][u];
                const float p0 = h1a[4*c], p1 = h1a[4*c+1], p2 = h1a[4*c+2], p3 = h1a[4*c+3];
                const float q0 = h1b[4*c], q1 = h1b[4*c+1], q2 = h1b[4*c+2], q3 = h1b[4*c+3];
                a2r_a = fmaf(p0, wr.x, a2r_a); a2r_a = fmaf(p1, wr.y, a2r_a);
                a2r_a = fmaf(p2, wr.z, a2r_a); a2r_a = fmaf(p3, wr.w, a2r_a);
                a2z_a = fmaf(p0, wz.x, a2z_a); a2z_a = fmaf(p1, wz.y, a2z_a);
                a2z_a = fmaf(p2, wz.z, a2z_a); a2z_a = fmaf(p3, wz.w, a2z_a);
                ai_a  = fmaf(p0, wn.x, ai_a);  ai_a  = fmaf(p1, wn.y, ai_a);
                ai_a  = fmaf(p2, wn.z, ai_a);  ai_a  = fmaf(p3, wn.w, ai_a);
                a2r_b = fmaf(q0, wr.x, a2r_b); a2r_b = fmaf(q1, wr.y, a2r_b);
                a2r_b = fmaf(q2, wr.z, a2r_b); a2r_b = fmaf(q3, wr.w, a2r_b);
                a2z_b = fmaf(q0, wz.x, a2z_b); a2z_b = fmaf(q1, wz.y, a2z_b);
                a2z_b = fmaf(q2, wz.z, a2z_b); a2z_b = fmaf(q3, wz.w, a2z_b);
                ai_b  = fmaf(q0, wn.x, ai_b);  ai_b  = fmaf(q1, wn.y, ai_b);
                ai_b  = fmaf(q2, wn.z, ai_b);  ai_b  = fmaf(q3, wn.w, ai_b);
            }
            const float r_a = fast_sig(a2r_a);
            const float z_a = fast_sig(a2z_a);
            const float n_a = fast_tanh(fmaf(r_a, a2n_a, ai_a));
            hn2_a = fmaf(z_a, hp2a - n_a, n_a);
            const float r_b = fast_sig(a2r_b);
            const float z_b = fast_sig(a2z_b);
            const float n_b = fast_tanh(fmaf(r_b, a2n_b, ai_b));
            hn2_b = fmaf(z_b, hp2b - n_b, n_b);
            hp2a = hn2_a; hp2b = hn2_b;
        }

        // ---- E) exchange h2 through shared ----
        if (sub < HID) {
            s_h2[grp_l][0][u] = hn2_a;
            s_h2[grp_l][1][u] = hn2_b;
        }
        __syncwarp();

        // ---- F) fc on idle lanes 12/13 ----
        if (sub == 12 || sub == 13) {
            const int bsel = sub - 12;
            const float4 c0 = *(const float4*)&s_h2[grp_l][bsel][0];
            const float4 c1 = *(const float4*)&s_h2[grp_l][bsel][4];
            const float4 c2 = *(const float4*)&s_h2[grp_l][bsel][8];
            float o = fcb;
            o = fmaf(fcw[0], c0.x, o); o = fmaf(fcw[1], c0.y, o);
            o = fmaf(fcw[2], c0.z, o); o = fmaf(fcw[3], c0.w, o);
            o = fmaf(fcw[4], c1.x, o); o = fmaf(fcw[5], c1.y, o);
            o = fmaf(fcw[6], c1.z, o); o = fmaf(fcw[7], c1.w, o);
            o = fmaf(fcw[8], c2.x, o); o = fmaf(fcw[9], c2.y, o);
            o = fmaf(fcw[10], c2.z, o); o = fmaf(fcw[11], c2.w, o);
            out[(size_t)(bsel ? b1 : b0) * SEQ + t] = o;
        }
        __syncwarp();
    }
}

extern "C" void kernel_launch(void* const* d_in, const int* in_sizes, int n_in,
                              void* d_out, int out_size) {
    const float* x     = (const float*)d_in[0];
    const float* w_ih0 = (const float*)d_in[1];
    const float* w_hh0 = (const float*)d_in[2];
    const float* b_ih0 = (const float*)d_in[3];
    const float* b_hh0 = (const float*)d_in[4];
    const float* w_ih1 = (const float*)d_in[5];
    const float* w_hh1 = (const float*)d_in[6];
    const float* b_ih1 = (const float*)d_in[7];
    const float* b_hh1 = (const float*)d_in[8];
    const float* fc_w  = (const float*)d_in[9];
    const float* fc_b  = (const float*)d_in[10];
    float* out = (float*)d_out;

    const int n_rows = BATCH * SEQ;
    gi0_kernel<<<n_rows / ROWS_PER_BLOCK, 128>>>(x, w_ih0, b_ih0);
    gru_scan_kernel<<<S_GRID, S_THREADS>>>(w_hh0, b_hh0, w_ih1, w_hh1,
                                           b_ih1, b_hh1, fc_w, fc_b, out);
}